// round 15
// baseline (speedup 1.0000x reference)
#include <cuda_runtime.h>
#include <cstdint>

#define BSZ  4
#define CDIM 256
#define NPIX 4096
#define CQD  32
#define ATTN_SCALE (1.0f/64.0f)   // 1/sqrt(4096)

// ---------------- scratch (device globals: allocation-free) ----------------
__device__ float g_q [BSZ*NPIX*CQD];    // [b][n][cq]  tf32-rounded
__device__ float g_kt[BSZ*CQD*NPIX];    // [b][cq][n]  tf32-rounded (K^T)
__device__ float g_vt[BSZ*CDIM*NPIX];   // [b][c][n]   tf32-rounded (V^T)

__device__ __forceinline__ float tf32r(float x) {
    uint32_t u;
    asm("cvt.rna.tf32.f32 %0, %1;" : "=r"(u) : "f"(x));
    return __uint_as_float(u);
}

// ---------------- cp.async helpers ----------------
__device__ __forceinline__ void cpa16(uint32_t dst, const void* src) {
    asm volatile("cp.async.cg.shared.global [%0], [%1], 16;" :: "r"(dst), "l"(src));
}
__device__ __forceinline__ void cpa_commit() {
    asm volatile("cp.async.commit_group;");
}
__device__ __forceinline__ void cpa_wait0() {
    asm volatile("cp.async.wait_group 0;" ::: "memory");
}
__device__ __forceinline__ void cpa_wait1() {
    asm volatile("cp.async.wait_group 1;" ::: "memory");
}

// ---------------- tf32 mma m16n8k8 ----------------
__device__ __forceinline__ void mma_tf32(float& d0, float& d1, float& d2, float& d3,
                                         uint32_t a0, uint32_t a1, uint32_t a2, uint32_t a3,
                                         uint32_t b0, uint32_t b1) {
    asm volatile(
        "mma.sync.aligned.m16n8k8.row.col.f32.tf32.tf32.f32 "
        "{%0,%1,%2,%3}, {%4,%5,%6,%7}, {%8,%9}, {%0,%1,%2,%3};"
        : "+f"(d0), "+f"(d1), "+f"(d2), "+f"(d3)
        : "r"(a0), "r"(a1), "r"(a2), "r"(a3), "r"(b0), "r"(b1));
}

// ============================================================================
// Kernel 1: fused QKV projection. Q [n][cq]; K,V stored TRANSPOSED.
// (unchanged from the 354us passing version)
// ============================================================================
__global__ __launch_bounds__(256) void qkv_kernel(
    const float* __restrict__ x,
    const float* __restrict__ Wq, const float* __restrict__ bq,
    const float* __restrict__ Wk, const float* __restrict__ bk,
    const float* __restrict__ Wv, const float* __restrict__ bv)
{
    __shared__ __align__(16) float Xs[32*128];
    __shared__ __align__(16) float Ws[32*68];

    const int t  = threadIdx.x;
    const int tm = t & 31;
    const int tj = t >> 5;
    const int n0 = blockIdx.x * 128;
    const int j0 = blockIdx.y * 64;
    const int b  = blockIdx.z;

    const int jj  = t >> 2;
    const int kkb = (t & 3) * 8;
    const int jglob = j0 + jj;
    const float* Wrow;
    if (jglob < 32)      Wrow = Wq + (size_t)jglob * CDIM;
    else if (jglob < 64) Wrow = Wk + (size_t)(jglob - 32) * CDIM;
    else                 Wrow = Wv + (size_t)(jglob - 64) * CDIM;

    float acc[4][8];
    #pragma unroll
    for (int i = 0; i < 4; i++)
        #pragma unroll
        for (int u = 0; u < 8; u++) acc[i][u] = 0.0f;

    for (int kc = 0; kc < CDIM; kc += 32) {
        #pragma unroll
        for (int i = 0; i < 4; i++) {
            int f   = t + i * 256;
            int row = f >> 5, c4 = f & 31;
            ((float4*)Xs)[f] =
                ((const float4*)(x + ((size_t)(b*CDIM + kc + row))*NPIX + n0))[c4];
        }
        #pragma unroll
        for (int u = 0; u < 8; u += 4) {
            float4 w = *((const float4*)(Wrow + kc + kkb + u));
            Ws[(kkb+u+0)*68 + jj] = w.x;
            Ws[(kkb+u+1)*68 + jj] = w.y;
            Ws[(kkb+u+2)*68 + jj] = w.z;
            Ws[(kkb+u+3)*68 + jj] = w.w;
        }
        __syncthreads();
        #pragma unroll
        for (int kk = 0; kk < 32; kk++) {
            float4 a  = *(const float4*)&Xs[kk*128 + tm*4];
            float4 w0 = *(const float4*)&Ws[kk*68 + tj*8];
            float4 w1 = *(const float4*)&Ws[kk*68 + tj*8 + 4];
            float av[4] = {a.x, a.y, a.z, a.w};
            float wv[8] = {w0.x, w0.y, w0.z, w0.w, w1.x, w1.y, w1.z, w1.w};
            #pragma unroll
            for (int i = 0; i < 4; i++)
                #pragma unroll
                for (int u = 0; u < 8; u++)
                    acc[i][u] = fmaf(av[i], wv[u], acc[i][u]);
        }
        __syncthreads();
    }

    #pragma unroll
    for (int u = 0; u < 8; u++) {
        int j = j0 + tj*8 + u;
        if (j >= 64) {
            float bias = bv[j-64];
            float4 vv = make_float4(tf32r(acc[0][u]+bias), tf32r(acc[1][u]+bias),
                                    tf32r(acc[2][u]+bias), tf32r(acc[3][u]+bias));
            *(float4*)(g_vt + ((size_t)(b*CDIM + (j-64)))*NPIX + n0 + tm*4) = vv;
        } else if (j >= 32) {
            float bias = bk[j-32];
            float4 kv = make_float4(tf32r(acc[0][u]+bias), tf32r(acc[1][u]+bias),
                                    tf32r(acc[2][u]+bias), tf32r(acc[3][u]+bias));
            *(float4*)(g_kt + ((size_t)(b*CQD + (j-32)))*NPIX + n0 + tm*4) = kv;
        } else {
            float bias = bq[j];
            #pragma unroll
            for (int i = 0; i < 4; i++)
                g_q[((size_t)(b*NPIX + n0 + tm*4 + i))*CQD + j] =
                    tf32r(acc[i][u] + bias);
        }
    }
}

// ============================================================================
// Kernel 2: fused attention, 256 threads/CTA, 2 CTAs/SM (occupancy fix).
// Per CTA: M=128 rows x N=128 channels (channel-half), 64 key tiles of 64.
// QK duplicated across the 2 channel-halves (cheap: 1/8 of PV flops).
//  QK: warp wm=w (0..7): rows wm*16..+15, ALL 64 keys (32 MMAs).
//      A = Q frags from gmem (registers). B = K [d][key] smem (double buf).
//  PV: warp (mh=w&3, nh=w>>2): rows mh*32..+31, cols nh*64..+63 (128 MMAs).
//      A = Ps frags, B = V^T [ch][key] smem (SINGLE buffer; its load is
//      hidden behind the QK phase via cp.async.wait_group 1).
// smem (floats):
//   Ks [2][32][72]  @0      (4608)
//   Ps [128][68]    @4608   (8704)
//   Vs [128][68]    @13312  (8704)
//   Lred [128]      @22016
// total 22144 floats = 88576 B  (x2 CTAs = 177 KB <= 228 KB)
// ============================================================================
#define SMEM_BYTES 88576

__global__ __launch_bounds__(256, 2) void attn_kernel(float* __restrict__ out)
{
    extern __shared__ __align__(16) float sm[];
    const uint32_t smb = (uint32_t)__cvta_generic_to_shared(sm);

    const uint32_t* Ks32A[2] = { (const uint32_t*)(sm),
                                 (const uint32_t*)(sm + 2304) };
    float* Ps = sm + 4608;
    const uint32_t* Ps32 = (const uint32_t*)Ps;
    float* Vs = sm + 13312;
    const uint32_t* Vs32 = (const uint32_t*)Vs;
    float* Lred = sm + 22016;

    const uint32_t ks_u32[2] = { smb, smb + 2304u*4u };
    const uint32_t vs_u32 = smb + 13312u*4u;

    const int t   = threadIdx.x;
    const int b   = blockIdx.y;
    const int n0  = (blockIdx.x & 31) * 128;     // query-row tile
    const int ch0 = (blockIdx.x >> 5) * 128;     // channel half
    const int w   = t >> 5;
    const int lan = t & 31;
    const int g   = lan >> 2;
    const int tq  = lan & 3;
    // QK role: warp wm owns rows wm*16..+15, all 64 keys
    const int wm  = w;
    // PV role
    const int mh  = w & 3;        // rows mh*32 .. +31
    const int nh  = w >> 2;       // cols nh*64 .. +63

    // ---- tile loaders ----
    auto issue_K = [&](int tilex, int buf) {
        const int key0 = tilex * 64;
        #pragma unroll
        for (int i = 0; i < 2; i++) {     // 512 float4 chunks, 2/thread
            int idx = t + i*256;
            int d = idx >> 4, k4 = idx & 15;
            cpa16(ks_u32[buf] + (uint32_t)(d*288 + k4*16),
                  g_kt + ((size_t)(b*CQD + d))*NPIX + key0 + k4*4);
        }
    };
    auto issue_V = [&](int tilex) {
        const int key0 = tilex * 64;
        #pragma unroll
        for (int i = 0; i < 8; i++) {     // 2048 float4 chunks, 8/thread
            int idx = t + i*256;
            int n = idx >> 4, k4 = idx & 15;
            cpa16(vs_u32 + (uint32_t)(n*272 + k4*16),
                  g_vt + ((size_t)(b*CDIM + ch0 + n))*NPIX + key0 + k4*4);
        }
    };

    // ---- prologue: K0, V0 in flight; Q A-frags from gmem ----
    issue_K(0, 0); cpa_commit();
    issue_V(0);    cpa_commit();

    uint32_t qa[4][4];
    {
        const float* q0 = g_q + ((size_t)(b*NPIX + n0 + wm*16 + g))*CQD;
        const float* q1 = g_q + ((size_t)(b*NPIX + n0 + wm*16 + 8 + g))*CQD;
        #pragma unroll
        for (int ks = 0; ks < 4; ks++) {
            qa[ks][0] = __float_as_uint(q0[ks*8 + tq]);
            qa[ks][1] = __float_as_uint(q1[ks*8 + tq]);
            qa[ks][2] = __float_as_uint(q0[ks*8 + tq + 4]);
            qa[ks][3] = __float_as_uint(q1[ks*8 + tq + 4]);
        }
    }

    float acc[2][8][4];
    #pragma unroll
    for (int mt = 0; mt < 2; mt++)
        #pragma unroll
        for (int nt = 0; nt < 8; nt++)
            #pragma unroll
            for (int q = 0; q < 4; q++) acc[mt][nt][q] = 0.0f;
    float l0 = 0.0f, l1 = 0.0f;

    for (int tile = 0; tile < 64; tile++) {
        const int bi = tile & 1;
        cpa_wait1();          // K(tile) landed (V(tile) may still be in flight)
        __syncthreads();      // Ks[bi] visible; prev PV's Ps reads done

        if (tile < 63) { issue_K(tile + 1, bi ^ 1); cpa_commit(); }

        // ---- QK phase: S = Q K^T via mma over all 64 keys; p -> Ps ----
        {
            const uint32_t* Ksb = Ks32A[bi];
            #pragma unroll
            for (int n8 = 0; n8 < 8; n8++) {
                float d0 = 0.0f, d1 = 0.0f, d2 = 0.0f, d3 = 0.0f;
                #pragma unroll
                for (int ks = 0; ks < 4; ks++) {
                    uint32_t kb0 = Ksb[(ks*8 + tq)*72     + n8*8 + g];
                    uint32_t kb1 = Ksb[(ks*8 + tq + 4)*72 + n8*8 + g];
                    mma_tf32(d0, d1, d2, d3,
                             qa[ks][0], qa[ks][1], qa[ks][2], qa[ks][3],
                             kb0, kb1);
                }
                float p00 = tf32r(__expf(d0 * ATTN_SCALE));
                float p01 = tf32r(__expf(d1 * ATTN_SCALE));
                float p10 = tf32r(__expf(d2 * ATTN_SCALE));
                float p11 = tf32r(__expf(d3 * ATTN_SCALE));
                l0 += p00 + p01;
                l1 += p10 + p11;
                *(float2*)&Ps[(wm*16 + g)*68     + n8*8 + 2*tq] =
                    make_float2(p00, p01);
                *(float2*)&Ps[(wm*16 + 8 + g)*68 + n8*8 + 2*tq] =
                    make_float2(p10, p11);
            }
        }
        // V(tile) must be landed before PV; t<63: pending={V(t),K(t+1)} -> wait1
        if (tile < 63) cpa_wait1(); else cpa_wait0();
        __syncthreads();      // Ps ready + Vs visible

        // ---- PV phase: O += P V via mma ----
        #pragma unroll
        for (int ks = 0; ks < 8; ks++) {
            uint32_t pa[2][4];
            #pragma unroll
            for (int mt = 0; mt < 2; mt++) {
                int row = mh*32 + mt*16;
                pa[mt][0] = Ps32[(row + g)*68     + ks*8 + tq];
                pa[mt][1] = Ps32[(row + 8 + g)*68 + ks*8 + tq];
                pa[mt][2] = Ps32[(row + g)*68     + ks*8 + tq + 4];
                pa[mt][3] = Ps32[(row + 8 + g)*68 + ks*8 + tq + 4];
            }
            #pragma unroll
            for (int nt = 0; nt < 8; nt++) {
                int n = nh*64 + nt*8 + g;
                uint32_t vb0 = Vs32[n*68 + ks*8 + tq];
                uint32_t vb1 = Vs32[n*68 + ks*8 + tq + 4];
                #pragma unroll
                for (int mt = 0; mt < 2; mt++)
                    mma_tf32(acc[mt][nt][0], acc[mt][nt][1],
                             acc[mt][nt][2], acc[mt][nt][3],
                             pa[mt][0], pa[mt][1], pa[mt][2], pa[mt][3],
                             vb0, vb1);
            }
        }
        __syncthreads();      // Vs fully consumed -> safe to refill
        if (tile < 63) { issue_V(tile + 1); cpa_commit(); }
    }

    // ---- l reduction: quad-shfl over tq; rows owned uniquely by warp wm ----
    #pragma unroll
    for (int off = 1; off < 4; off <<= 1) {
        l0 += __shfl_xor_sync(0xffffffffu, l0, off);
        l1 += __shfl_xor_sync(0xffffffffu, l1, off);
    }
    if (tq == 0) {
        Lred[wm*16 + g]     = l0;
        Lred[wm*16 + 8 + g] = l1;
    }
    __syncthreads();

    // ---- epilogue: divide by l, write out[b][n][ch0+...] ----
    #pragma unroll
    for (int mt = 0; mt < 2; mt++) {
        int r0 = mh*32 + mt*16 + g;
        int r1 = r0 + 8;
        float li0 = 1.0f / Lred[r0];
        float li1 = 1.0f / Lred[r1];
        float* o0 = out + ((size_t)(b*NPIX + n0 + r0))*CDIM + ch0;
        float* o1 = out + ((size_t)(b*NPIX + n0 + r1))*CDIM + ch0;
        #pragma unroll
        for (int nt = 0; nt < 8; nt++) {
            int c = nh*64 + nt*8 + tq*2;
            *(float2*)&o0[c] = make_float2(acc[mt][nt][0]*li0, acc[mt][nt][1]*li0);
            *(float2*)&o1[c] = make_float2(acc[mt][nt][2]*li1, acc[mt][nt][3]*li1);
        }
    }
}

// ============================================================================
extern "C" void kernel_launch(void* const* d_in, const int* in_sizes, int n_in,
                              void* d_out, int out_size)
{
    const float* x  = (const float*)d_in[0];
    const float* Wq = (const float*)d_in[1];
    const float* bq = (const float*)d_in[2];
    const float* Wk = (const float*)d_in[3];
    const float* bk = (const float*)d_in[4];
    const float* Wv = (const float*)d_in[5];
    const float* bv = (const float*)d_in[6];
    float* out = (float*)d_out;

    cudaFuncSetAttribute(attn_kernel,
                         cudaFuncAttributeMaxDynamicSharedMemorySize, SMEM_BYTES);

    qkv_kernel<<<dim3(32, 5, 4), 256>>>(x, Wq, bq, Wk, bk, Wv, bv);
    attn_kernel<<<dim3(64, 4), 256, SMEM_BYTES>>>(out);
}